// round 3
// baseline (speedup 1.0000x reference)
#include <cuda_runtime.h>

#define GRIDN 16384
#define GMASK 16383
#define MX    4096
#define NLAYER 8
#define NTHREADS 256
#define NWARP 8
#define NBLK 296   // 2 * 148; single wave on both 148- and 152-SM sm_103a parts

__device__ __forceinline__ float sigf(float v) {
    return 1.0f / (1.0f + __expf(-v));
}

__device__ __forceinline__ float lerpf(float a, float b, float w) {
    return fmaf(w, b - a, a);   // a + w*(b-a)
}

__global__ __launch_bounds__(NTHREADS, 2)
void ASIC_44186623541335_kernel(const float* __restrict__ x, const float* __restrict__ tg,
                                float* __restrict__ out, int base, int extra, int srows)
{
    extern __shared__ float sm[];
    float* s_state = sm;                      // 2 * srows * 32 floats (ping-pong, [cell][batch])
    float* s_tw    = sm + 2 * srows * 32;     // srows * 36 floats ([cell][c], pitch 36)
    float* s_x     = s_tw + srows * 36;       // [m][batch] pitch 33

    const int blk  = blockIdx.x;
    const int T    = base + (blk < extra ? 1 : 0);
    const int start = blk * base + (blk < extra ? blk : extra);
    const int tid  = threadIdx.x;
    const int lane = tid & 31;   // lane == batch index
    const int wid  = tid >> 5;

    // ---- stage x tile (m window with ring wrap), [m][batch] pitch 33 ----
    const int m_lo = (start - 16) >> 2;                   // arithmetic floor
    const int nmv  = ((start + T + 15) >> 2) - m_lo + 1;
    for (int mi0 = 0; mi0 < nmv; mi0 += 32) {
        for (int i = tid; i < 32 * 32; i += NTHREADS) {
            int mi = mi0 + (i & 31), bb = i >> 5;
            if (mi < nmv) {
                int m = (m_lo + mi) & (MX - 1);
                s_x[mi * 33 + bb] = x[bb * MX + m];
            }
        }
    }
    __syncthreads();

    // ---- layer 0: initial state is x at every 4th cell, zeros elsewhere.
    // Zero fold-weights select table entries -> 1..3 lerps, 2..4 table loads.
    // bit for kernel offset i is 2^(4-i); nonzero neighbor offsets: i == (2 - n) mod 4.
    {
        const int lo = -14;
        const int cnt = T + 28;
        const int chunk = (cnt + NWARP - 1) / NWARP;
        int c0 = lo + wid * chunk;
        int c1 = min(c0 + chunk, lo + cnt);
        for (int rel = c0; rel < c1; rel++) {
            int graw = start + rel;
            int g = graw & GMASK;
            int r4 = graw & 3;
            float t0 = sigf(tg[g]);
            float res;
            if (r4 == 2) {  // two nonzero neighbors: i=0 (bit 16) and i=4 (bit 1)
                float t16 = sigf(tg[16 * GRIDN + g]);
                float t1  = sigf(tg[1  * GRIDN + g]);
                float t17 = sigf(tg[17 * GRIDN + g]);
                float sa = s_x[(((graw - 2) >> 2) - m_lo) * 33 + lane];
                float sb = s_x[(((graw + 2) >> 2) - m_lo) * 33 + lane];
                float a = lerpf(t0, t16, sa);
                float b = lerpf(t1, t17, sa);
                res = lerpf(a, b, sb);
            } else {
                int cidx, doff;
                if (r4 == 0)      { cidx = 4; doff =  0; }  // i=2 -> bit 4
                else if (r4 == 1) { cidx = 8; doff = -1; }  // i=1 -> bit 8
                else              { cidx = 2; doff =  1; }  // i=3 -> bit 2
                float t1 = sigf(tg[cidx * GRIDN + g]);
                float s = s_x[(((graw + doff) >> 2) - m_lo) * 33 + lane];
                res = lerpf(t0, t1, s);
            }
            s_state[(rel + 14) * 32 + lane] = __saturatef(res);
        }
    }

    // ---- layers 1..7: shrinking halo, table from shared, binary-tree fold ----
    int cur = 0;
    for (int l = 1; l < NLAYER; l++) {
        __syncthreads();
        const int h = 2 * (NLAYER - 1 - l);
        const int lo = -h;
        const int cnt = T + 2 * h;
        const float* tgl = tg + l * (32 * GRIDN);
        {   // load+sigmoid+transpose tw[l] for rows [lo, lo+cnt): coalesced in n
            const int rsub = tid & 63;
            const int csub = tid >> 6;
            for (int c = csub; c < 32; c += 4) {
                const float* tgc = tgl + c * GRIDN;
                for (int r = rsub; r < cnt; r += 64) {
                    int g = (start + lo + r) & GMASK;
                    s_tw[(lo + r + 14) * 36 + c] = sigf(tgc[g]);
                }
            }
        }
        __syncthreads();
        const float* sin_ = s_state + cur * srows * 32;
        float*       sout = s_state + (cur ^ 1) * srows * 32;
        const int chunk = (cnt + NWARP - 1) / NWARP;
        int c0 = lo + wid * chunk;
        int c1 = min(c0 + chunk, lo + cnt);
        if (c0 < c1) {
            // sliding 5-wide state window: 1 new LDS per cell
            float w0 = sin_[(c0 + 12) * 32 + lane];
            float w1 = sin_[(c0 + 13) * 32 + lane];
            float w2 = sin_[(c0 + 14) * 32 + lane];
            float w3 = sin_[(c0 + 15) * 32 + lane];
            for (int cell = c0; cell < c1; cell++) {
                float w4 = sin_[(cell + 16) * 32 + lane];
                // table: 32 floats via 8x 16B shared loads (warp-uniform broadcast)
                const float4* tp = (const float4*)(s_tw + (cell + 14) * 36);
                float t[32];
                #pragma unroll
                for (int k = 0; k < 8; k++) {
                    float4 q = tp[k];
                    t[4 * k + 0] = q.x; t[4 * k + 1] = q.y;
                    t[4 * k + 2] = q.z; t[4 * k + 3] = q.w;
                }
                // fold MSB->LSB: neighbor -2 (bit16), -1 (bit8), 0 (bit4), +1 (bit2), +2 (bit1)
                #pragma unroll
                for (int k = 0; k < 16; k++) t[k] = lerpf(t[k], t[k + 16], w0);
                #pragma unroll
                for (int k = 0; k < 8; k++)  t[k] = lerpf(t[k], t[k + 8],  w1);
                #pragma unroll
                for (int k = 0; k < 4; k++)  t[k] = lerpf(t[k], t[k + 4],  w2);
                t[0] = lerpf(t[0], t[2], w3);
                t[1] = lerpf(t[1], t[3], w3);
                float res = __saturatef(lerpf(t[0], t[1], w4));
                sout[(cell + 14) * 32 + lane] = res;
                w0 = w1; w1 = w2; w2 = w3; w3 = w4;
            }
        }
        cur ^= 1;
    }
    __syncthreads();

    // ---- output: out[b][m] = state[4m] for 4m in [start, start+T) ----
    const float* sf = s_state + cur * srows * 32;
    const int m0  = (start + 3) >> 2;
    const int nmo = ((start + T + 3) >> 2) - m0;
    for (int mi0 = 0; mi0 < nmo; mi0 += 16) {
        for (int i = tid; i < 32 * 16; i += NTHREADS) {
            int mi = mi0 + (i & 15), bb = i >> 4;
            if (mi < nmo) {
                int m = m0 + mi;
                out[bb * MX + m] = sf[(4 * m - start + 14) * 32 + bb];
            }
        }
    }
}

extern "C" void kernel_launch(void* const* d_in, const int* in_sizes, int n_in,
                              void* d_out, int out_size)
{
    const float* x  = (const float*)d_in[0];
    const float* tg = (const float*)d_in[1];
    float* out = (float*)d_out;

    const int nblk  = NBLK;
    const int base  = GRIDN / nblk;          // 55
    const int extra = GRIDN - base * nblk;   // 104
    const int tmax  = base + 1;              // 56
    const int srows = tmax + 28;             // 84
    const int nx    = tmax / 4 + 11;         // 25
    size_t smem = (size_t)(2 * srows * 32 + srows * 36 + nx * 33) * sizeof(float); // ~36.9 KB

    ASIC_44186623541335_kernel<<<nblk, NTHREADS, smem>>>(x, tg, out, base, extra, srows);
}

// round 7
// speedup vs baseline: 1.2740x; 1.2740x over previous
#include <cuda_runtime.h>

#define GRIDN 16384
#define GMASK 16383
#define MX    4096
#define NLAYER 8
#define NTHREADS 512
#define NWARP 16
#define NBLK 296   // 2 * 148; single wave on both 148- and 152-SM sm_103a parts

__device__ __forceinline__ float sigf(float v) {
    return __fdividef(1.0f, 1.0f + __expf(-v));
}

__device__ __forceinline__ float lerpf(float a, float b, float w) {
    return fmaf(w, b - a, a);   // a + w*(b-a)
}

__global__ __launch_bounds__(NTHREADS, 2)
void ASIC_44186623541335_kernel(const float* __restrict__ x, const float* __restrict__ tg,
                                float* __restrict__ out, int base, int extra, int srows)
{
    extern __shared__ float sm[];
    float* s_state = sm;                      // 2 * srows * 32 floats (ping-pong, [cell][batch])
    float* s_tw    = sm + 2 * srows * 32;     // srows * 36 floats ([cell][c], pitch 36)
    float* s_x     = s_tw + srows * 36;       // [m][batch] pitch 33

    const int blk  = blockIdx.x;
    const int T    = base + (blk < extra ? 1 : 0);
    const int start = blk * base + (blk < extra ? blk : extra);
    const int tid  = threadIdx.x;
    const int lane = tid & 31;   // lane == batch index
    const int wid  = tid >> 5;

    // ---- stage x tile (m window with ring wrap), [m][batch] pitch 33 ----
    const int m_lo = (start - 16) >> 2;                   // arithmetic floor
    const int nmv  = ((start + T + 15) >> 2) - m_lo + 1;
    for (int mi0 = 0; mi0 < nmv; mi0 += 32) {
        for (int i = tid; i < 32 * 32; i += NTHREADS) {
            int mi = mi0 + (i & 31), bb = i >> 5;
            if (mi < nmv) {
                int m = (m_lo + mi) & (MX - 1);
                s_x[mi * 33 + bb] = x[bb * MX + m];
            }
        }
    }
    __syncthreads();

    // ---- layer 0: initial state is x at every 4th cell, zeros elsewhere.
    // Zero fold-weights select table entries -> 1..3 lerps, 2..4 table loads.
    // bit for kernel offset i is 2^(4-i); nonzero neighbor offsets: i == (2 - n) mod 4.
    {
        const int lo = -14;
        const int cnt = T + 28;
        const int chunk = (cnt + NWARP - 1) / NWARP;
        int c0 = lo + wid * chunk;
        int c1 = min(c0 + chunk, lo + cnt);
        for (int rel = c0; rel < c1; rel++) {
            int graw = start + rel;
            int g = graw & GMASK;
            int r4 = graw & 3;
            float t0 = sigf(tg[g]);
            float res;
            if (r4 == 2) {  // two nonzero neighbors: i=0 (bit 16) and i=4 (bit 1)
                float t16 = sigf(tg[16 * GRIDN + g]);
                float t1  = sigf(tg[1  * GRIDN + g]);
                float t17 = sigf(tg[17 * GRIDN + g]);
                float sa = s_x[(((graw - 2) >> 2) - m_lo) * 33 + lane];
                float sb = s_x[(((graw + 2) >> 2) - m_lo) * 33 + lane];
                float a = lerpf(t0, t16, sa);
                float b = lerpf(t1, t17, sa);
                res = lerpf(a, b, sb);
            } else {
                int cidx, doff;
                if (r4 == 0)      { cidx = 4; doff =  0; }  // i=2 -> bit 4
                else if (r4 == 1) { cidx = 8; doff = -1; }  // i=1 -> bit 8
                else              { cidx = 2; doff =  1; }  // i=3 -> bit 2
                float t1 = sigf(tg[cidx * GRIDN + g]);
                float s = s_x[(((graw + doff) >> 2) - m_lo) * 33 + lane];
                res = lerpf(t0, t1, s);
            }
            s_state[(rel + 14) * 32 + lane] = __saturatef(res);
        }
    }

    // ---- layers 1..7: shrinking halo, table from shared, binary-tree fold ----
    int cur = 0;
    for (int l = 1; l < NLAYER; l++) {
        __syncthreads();
        const int h = 2 * (NLAYER - 1 - l);
        const int lo = -h;
        const int cnt = T + 2 * h;
        const float* tgl = tg + l * (32 * GRIDN);
        {   // load+sigmoid+transpose tw[l] for rows [lo, lo+cnt): coalesced in n
            const int rsub = tid & 127;
            const int csub = tid >> 7;
            for (int c = csub; c < 32; c += 4) {
                const float* tgc = tgl + c * GRIDN;
                for (int r = rsub; r < cnt; r += 128) {
                    int g = (start + lo + r) & GMASK;
                    s_tw[(lo + r + 14) * 36 + c] = sigf(tgc[g]);
                }
            }
        }
        __syncthreads();
        const float* sin_ = s_state + cur * srows * 32;
        float*       sout = s_state + (cur ^ 1) * srows * 32;
        const int chunk = (cnt + NWARP - 1) / NWARP;
        int c0 = lo + wid * chunk;
        int c1 = min(c0 + chunk, lo + cnt);
        if (c0 < c1) {
            // sliding 5-wide state window: 1 new LDS per cell
            float w0 = sin_[(c0 + 12) * 32 + lane];
            float w1 = sin_[(c0 + 13) * 32 + lane];
            float w2 = sin_[(c0 + 14) * 32 + lane];
            float w3 = sin_[(c0 + 15) * 32 + lane];
            for (int cell = c0; cell < c1; cell++) {
                float w4 = sin_[(cell + 16) * 32 + lane];
                // table: 32 floats via 8x 16B shared loads (warp-uniform broadcast)
                const float4* tp = (const float4*)(s_tw + (cell + 14) * 36);
                float t[32];
                #pragma unroll
                for (int k = 0; k < 8; k++) {
                    float4 q = tp[k];
                    t[4 * k + 0] = q.x; t[4 * k + 1] = q.y;
                    t[4 * k + 2] = q.z; t[4 * k + 3] = q.w;
                }
                // fold MSB->LSB: neighbor -2 (bit16), -1 (bit8), 0 (bit4), +1 (bit2), +2 (bit1)
                #pragma unroll
                for (int k = 0; k < 16; k++) t[k] = lerpf(t[k], t[k + 16], w0);
                #pragma unroll
                for (int k = 0; k < 8; k++)  t[k] = lerpf(t[k], t[k + 8],  w1);
                #pragma unroll
                for (int k = 0; k < 4; k++)  t[k] = lerpf(t[k], t[k + 4],  w2);
                t[0] = lerpf(t[0], t[2], w3);
                t[1] = lerpf(t[1], t[3], w3);
                float res = __saturatef(lerpf(t[0], t[1], w4));
                sout[(cell + 14) * 32 + lane] = res;
                w0 = w1; w1 = w2; w2 = w3; w3 = w4;
            }
        }
        cur ^= 1;
    }
    __syncthreads();

    // ---- output: out[b][m] = state[4m] for 4m in [start, start+T) ----
    const float* sf = s_state + cur * srows * 32;
    const int m0  = (start + 3) >> 2;
    const int nmo = ((start + T + 3) >> 2) - m0;
    for (int mi0 = 0; mi0 < nmo; mi0 += 16) {
        for (int i = tid; i < 32 * 16; i += NTHREADS) {
            int mi = mi0 + (i & 15), bb = i >> 4;
            if (mi < nmo) {
                int m = m0 + mi;
                out[bb * MX + m] = sf[(4 * m - start + 14) * 32 + bb];
            }
        }
    }
}

extern "C" void kernel_launch(void* const* d_in, const int* in_sizes, int n_in,
                              void* d_out, int out_size)
{
    const float* x  = (const float*)d_in[0];
    const float* tg = (const float*)d_in[1];
    float* out = (float*)d_out;

    const int nblk  = NBLK;
    const int base  = GRIDN / nblk;          // 55
    const int extra = GRIDN - base * nblk;   // 104
    const int tmax  = base + 1;              // 56
    const int srows = tmax + 28;             // 84
    const int nx    = tmax / 4 + 11;         // 25
    size_t smem = (size_t)(2 * srows * 32 + srows * 36 + nx * 33) * sizeof(float); // ~36.9 KB

    ASIC_44186623541335_kernel<<<nblk, NTHREADS, smem>>>(x, tg, out, base, extra, srows);
}

// round 8
// speedup vs baseline: 1.7404x; 1.3661x over previous
#include <cuda_runtime.h>

#define GRIDN 16384
#define GMASK 16383
#define MX    4096
#define NLAYER 8
#define NTHREADS 512
#define NWARP 16
#define NBLK 296   // 2 * 148; single wave on both 148- and 152-SM sm_103a parts

__device__ __forceinline__ float sigf(float v) {
    return __fdividef(1.0f, 1.0f + __expf(-v));
}

__device__ __forceinline__ float lerpf(float a, float b, float w) {
    return fmaf(w, b - a, a);   // a + w*(b-a)
}

__global__ __launch_bounds__(NTHREADS, 2)
void ASIC_44186623541335_kernel(const float* __restrict__ x, const float* __restrict__ tg,
                                float* __restrict__ out, int base, int extra, int srows)
{
    extern __shared__ float sm[];
    float* s_state = sm;                      // 2 * srows * 32 (ping-pong, [cell][batch])
    float* s_tw    = sm + 2 * srows * 32;     // 2 * srows * 36 (double-buffered, [cell][c])
    float* s_x     = s_tw + 2 * srows * 36;   // [m][batch] pitch 33

    const int blk  = blockIdx.x;
    const int T    = base + (blk < extra ? 1 : 0);
    const int start = blk * base + (blk < extra ? blk : extra);
    const int tid  = threadIdx.x;
    const int lane = tid & 31;   // lane == batch index
    const int wid  = tid >> 5;

    // prefetch mapping for tw staging: c = tid>>4 (0..31), r = (tid&15) + 16k, k<5 (covers cnt<=80)
    const int pc  = tid >> 4;
    const int pr0 = tid & 15;
    const float* tg_pc = tg + pc * GRIDN;
    float v[5];

    // ---- prologue: issue LDGs for layer 1's tables (latency hidden by x-stage + layer0) ----
    {
        const int h = 12, cnt = T + 24;               // layer 1 halo
        const float* tgl = tg_pc + 1 * (32 * GRIDN);
        #pragma unroll
        for (int k = 0; k < 5; k++) {
            int r = pr0 + 16 * k;
            if (r < cnt) v[k] = tgl[(start - h + r) & GMASK];
        }
    }

    // ---- stage x tile (m window with ring wrap), [m][batch] pitch 33 ----
    const int m_lo = (start - 16) >> 2;                   // arithmetic floor
    const int nmv  = ((start + T + 15) >> 2) - m_lo + 1;
    for (int mi0 = 0; mi0 < nmv; mi0 += 32) {
        for (int i = tid; i < 32 * 32; i += NTHREADS) {
            int mi = mi0 + (i & 31), bb = i >> 5;
            if (mi < nmv) {
                int m = (m_lo + mi) & (MX - 1);
                s_x[mi * 33 + bb] = x[bb * MX + m];
            }
        }
    }
    __syncthreads();

    // ---- layer 0: initial state is x at every 4th cell, zeros elsewhere.
    // Zero fold-weights select table entries -> 1..3 lerps, 2..4 table loads.
    {
        const int lo = -14;
        const int cnt = T + 28;
        const int chunk = (cnt + NWARP - 1) / NWARP;
        int c0 = lo + wid * chunk;
        int c1 = min(c0 + chunk, lo + cnt);
        for (int rel = c0; rel < c1; rel++) {
            int graw = start + rel;
            int g = graw & GMASK;
            int r4 = graw & 3;
            float t0 = sigf(tg[g]);
            float res;
            if (r4 == 2) {  // two nonzero neighbors: i=0 (bit 16) and i=4 (bit 1)
                float t16 = sigf(tg[16 * GRIDN + g]);
                float t1  = sigf(tg[1  * GRIDN + g]);
                float t17 = sigf(tg[17 * GRIDN + g]);
                float sa = s_x[(((graw - 2) >> 2) - m_lo) * 33 + lane];
                float sb = s_x[(((graw + 2) >> 2) - m_lo) * 33 + lane];
                float a = lerpf(t0, t16, sa);
                float b = lerpf(t1, t17, sa);
                res = lerpf(a, b, sb);
            } else {
                int cidx, doff;
                if (r4 == 0)      { cidx = 4; doff =  0; }  // i=2 -> bit 4
                else if (r4 == 1) { cidx = 8; doff = -1; }  // i=1 -> bit 8
                else              { cidx = 2; doff =  1; }  // i=3 -> bit 2
                float t1 = sigf(tg[cidx * GRIDN + g]);
                float s = s_x[(((graw + doff) >> 2) - m_lo) * 33 + lane];
                res = lerpf(t0, t1, s);
            }
            s_state[(rel + 14) * 32 + lane] = __saturatef(res);
        }
    }

    // ---- layers 1..7: pipelined staging (1 barrier/layer), binary-tree fold ----
    int cur = 0;
    for (int l = 1; l < NLAYER; l++) {
        const int h = 2 * (NLAYER - 1 - l);
        const int lo = -h;
        const int cnt = T + 2 * h;
        float* twb = s_tw + (l & 1) * srows * 36;

        // store prefetched tables (sigmoid applied) into this layer's buffer
        #pragma unroll
        for (int k = 0; k < 5; k++) {
            int r = pr0 + 16 * k;
            if (r < cnt) twb[(lo + r + 14) * 36 + pc] = sigf(v[k]);
        }
        // issue LDGs for next layer's tables; latency drains under the fold below
        if (l < NLAYER - 1) {
            const int hn = h - 2, cntn = cnt - 4;
            const float* tgln = tg_pc + (l + 1) * (32 * GRIDN);
            #pragma unroll
            for (int k = 0; k < 5; k++) {
                int r = pr0 + 16 * k;
                if (r < cntn) v[k] = tgln[(start - hn + r) & GMASK];
            }
        }
        __syncthreads();   // tw[l] visible + state[l-1] complete

        const float* sin_ = s_state + cur * srows * 32;
        float*       sout = s_state + (cur ^ 1) * srows * 32;
        const int chunk = (cnt + NWARP - 1) / NWARP;
        int c0 = lo + wid * chunk;
        int c1 = min(c0 + chunk, lo + cnt);
        if (c0 < c1) {
            // sliding 5-wide state window: 1 new LDS per cell
            float w0 = sin_[(c0 + 12) * 32 + lane];
            float w1 = sin_[(c0 + 13) * 32 + lane];
            float w2 = sin_[(c0 + 14) * 32 + lane];
            float w3 = sin_[(c0 + 15) * 32 + lane];
            for (int cell = c0; cell < c1; cell++) {
                float w4 = sin_[(cell + 16) * 32 + lane];
                // table: 32 floats via 8x 16B shared loads (warp-uniform broadcast)
                const float4* tp = (const float4*)(twb + (cell + 14) * 36);
                float t[32];
                #pragma unroll
                for (int k = 0; k < 8; k++) {
                    float4 q = tp[k];
                    t[4 * k + 0] = q.x; t[4 * k + 1] = q.y;
                    t[4 * k + 2] = q.z; t[4 * k + 3] = q.w;
                }
                // fold MSB->LSB: neighbor -2 (bit16), -1 (bit8), 0 (bit4), +1 (bit2), +2 (bit1)
                #pragma unroll
                for (int k = 0; k < 16; k++) t[k] = lerpf(t[k], t[k + 16], w0);
                #pragma unroll
                for (int k = 0; k < 8; k++)  t[k] = lerpf(t[k], t[k + 8],  w1);
                #pragma unroll
                for (int k = 0; k < 4; k++)  t[k] = lerpf(t[k], t[k + 4],  w2);
                t[0] = lerpf(t[0], t[2], w3);
                t[1] = lerpf(t[1], t[3], w3);
                float res = __saturatef(lerpf(t[0], t[1], w4));
                sout[(cell + 14) * 32 + lane] = res;
                w0 = w1; w1 = w2; w2 = w3; w3 = w4;
            }
        }
        cur ^= 1;
    }
    __syncthreads();

    // ---- output: out[b][m] = state[4m] for 4m in [start, start+T) ----
    const float* sf = s_state + cur * srows * 32;
    const int m0  = (start + 3) >> 2;
    const int nmo = ((start + T + 3) >> 2) - m0;
    for (int mi0 = 0; mi0 < nmo; mi0 += 16) {
        for (int i = tid; i < 32 * 16; i += NTHREADS) {
            int mi = mi0 + (i & 15), bb = i >> 4;
            if (mi < nmo) {
                int m = m0 + mi;
                out[bb * MX + m] = sf[(4 * m - start + 14) * 32 + bb];
            }
        }
    }
}

extern "C" void kernel_launch(void* const* d_in, const int* in_sizes, int n_in,
                              void* d_out, int out_size)
{
    const float* x  = (const float*)d_in[0];
    const float* tg = (const float*)d_in[1];
    float* out = (float*)d_out;

    const int nblk  = NBLK;
    const int base  = GRIDN / nblk;          // 55
    const int extra = GRIDN - base * nblk;   // 104
    const int tmax  = base + 1;              // 56
    const int srows = tmax + 28;             // 84
    const int nx    = tmax / 4 + 11;         // 25
    size_t smem = (size_t)(2 * srows * 32 + 2 * srows * 36 + nx * 33) * sizeof(float); // ~49 KB

    static int smem_set = 0;
    if (!smem_set) {
        cudaFuncSetAttribute(ASIC_44186623541335_kernel,
                             cudaFuncAttributeMaxDynamicSharedMemorySize, (int)smem);
        smem_set = 1;
    }
    ASIC_44186623541335_kernel<<<nblk, NTHREADS, smem>>>(x, tg, out, base, extra, srows);
}

// round 9
// speedup vs baseline: 1.8835x; 1.0823x over previous
#include <cuda_runtime.h>

#define GRIDN 16384
#define GMASK 16383
#define MX    4096
#define NLAYER 8
#define NTHREADS 512
#define NWARP 16
#define NBLK 296   // 2 * 148; single wave on both 148- and 152-SM sm_103a parts

__device__ __forceinline__ float sigf(float v) {
    return __fdividef(1.0f, 1.0f + __expf(-v));
}

__device__ __forceinline__ float lerpf(float a, float b, float w) {
    return fmaf(w, b - a, a);   // a + w*(b-a)
}

__device__ __forceinline__ unsigned long long pk2(float a) {
    unsigned long long r;
    asm("mov.b64 %0, {%1, %2};" : "=l"(r) : "f"(a), "f"(a));
    return r;
}

// packed lerp over two independent (lo,hi) pairs: r = lo*(1-s) + hi*s
__device__ __forceinline__ unsigned long long pklerp(unsigned long long lo, unsigned long long hi,
                                                     unsigned long long om, unsigned long long sp) {
    unsigned long long t, r;
    asm("mul.rn.f32x2 %0, %1, %2;" : "=l"(t) : "l"(lo), "l"(om));
    asm("fma.rn.f32x2 %0, %1, %2, %3;" : "=l"(r) : "l"(hi), "l"(sp), "l"(t));
    return r;
}

__global__ __launch_bounds__(NTHREADS, 2)
void ASIC_44186623541335_kernel(const float* __restrict__ x, const float* __restrict__ tg,
                                float* __restrict__ out, int base, int extra, int srows)
{
    extern __shared__ float sm[];
    float* s_state = sm;                      // 2 * srows * 32 (ping-pong, [cell][batch])
    float* s_tw    = sm + 2 * srows * 32;     // 2 * srows * 36 (double-buffered, [cell][c])
    float* s_x     = s_tw + 2 * srows * 36;   // [m][batch] pitch 33

    const int blk  = blockIdx.x;
    const int T    = base + (blk < extra ? 1 : 0);
    const int start = blk * base + (blk < extra ? blk : extra);
    const int tid  = threadIdx.x;
    const int lane = tid & 31;   // lane == batch index
    const int wid  = tid >> 5;

    // prefetch mapping for tw staging: c = tid>>4 (0..31), r = (tid&15) + 16k, k<5 (covers cnt<=80)
    const int pc  = tid >> 4;
    const int pr0 = tid & 15;
    const float* tg_pc = tg + pc * GRIDN;
    float v[5];

    // ---- prologue: issue LDGs for layer 1's tables (latency hidden by x-stage + layer0) ----
    {
        const int h = 12, cnt = T + 24;               // layer 1 halo
        const float* tgl = tg_pc + 1 * (32 * GRIDN);
        #pragma unroll
        for (int k = 0; k < 5; k++) {
            int r = pr0 + 16 * k;
            if (r < cnt) v[k] = tgl[(start - h + r) & GMASK];
        }
    }

    // ---- stage x tile (m window with ring wrap), [m][batch] pitch 33 ----
    const int m_lo = (start - 16) >> 2;                   // arithmetic floor
    const int nmv  = ((start + T + 15) >> 2) - m_lo + 1;
    for (int mi0 = 0; mi0 < nmv; mi0 += 32) {
        for (int i = tid; i < 32 * 32; i += NTHREADS) {
            int mi = mi0 + (i & 31), bb = i >> 5;
            if (mi < nmv) {
                int m = (m_lo + mi) & (MX - 1);
                s_x[mi * 33 + bb] = x[bb * MX + m];
            }
        }
    }
    __syncthreads();

    // ---- layer 0: initial state is x at every 4th cell, zeros elsewhere.
    // Zero fold-weights select table entries -> 1..3 lerps, 2..4 table loads.
    {
        const int lo = -14;
        const int cnt = T + 28;
        const int chunk = (cnt + NWARP - 1) / NWARP;
        int c0 = lo + wid * chunk;
        int c1 = min(c0 + chunk, lo + cnt);
        for (int rel = c0; rel < c1; rel++) {
            int graw = start + rel;
            int g = graw & GMASK;
            int r4 = graw & 3;
            float t0 = sigf(tg[g]);
            float res;
            if (r4 == 2) {  // two nonzero neighbors: i=0 (bit 16) and i=4 (bit 1)
                float t16 = sigf(tg[16 * GRIDN + g]);
                float t1  = sigf(tg[1  * GRIDN + g]);
                float t17 = sigf(tg[17 * GRIDN + g]);
                float sa = s_x[(((graw - 2) >> 2) - m_lo) * 33 + lane];
                float sb = s_x[(((graw + 2) >> 2) - m_lo) * 33 + lane];
                float a = lerpf(t0, t16, sa);
                float b = lerpf(t1, t17, sa);
                res = lerpf(a, b, sb);
            } else {
                int cidx, doff;
                if (r4 == 0)      { cidx = 4; doff =  0; }  // i=2 -> bit 4
                else if (r4 == 1) { cidx = 8; doff = -1; }  // i=1 -> bit 8
                else              { cidx = 2; doff =  1; }  // i=3 -> bit 2
                float t1 = sigf(tg[cidx * GRIDN + g]);
                float s = s_x[(((graw + doff) >> 2) - m_lo) * 33 + lane];
                res = lerpf(t0, t1, s);
            }
            s_state[(rel + 14) * 32 + lane] = __saturatef(res);
        }
    }

    // ---- layers 1..7: pipelined staging (1 barrier/layer), packed f32x2 fold ----
    int cur = 0;
    for (int l = 1; l < NLAYER; l++) {
        const int h = 2 * (NLAYER - 1 - l);
        const int lo = -h;
        const int cnt = T + 2 * h;
        float* twb = s_tw + (l & 1) * srows * 36;

        // store prefetched tables (sigmoid applied) into this layer's buffer
        #pragma unroll
        for (int k = 0; k < 5; k++) {
            int r = pr0 + 16 * k;
            if (r < cnt) twb[(lo + r + 14) * 36 + pc] = sigf(v[k]);
        }
        // issue LDGs for next layer's tables; latency drains under the fold below
        if (l < NLAYER - 1) {
            const int hn = h - 2, cntn = cnt - 4;
            const float* tgln = tg_pc + (l + 1) * (32 * GRIDN);
            #pragma unroll
            for (int k = 0; k < 5; k++) {
                int r = pr0 + 16 * k;
                if (r < cntn) v[k] = tgln[(start - hn + r) & GMASK];
            }
        }
        __syncthreads();   // tw[l] visible + state[l-1] complete

        const float* sin_ = s_state + cur * srows * 32;
        float*       sout = s_state + (cur ^ 1) * srows * 32;
        const int chunk = (cnt + NWARP - 1) / NWARP;
        int c0 = lo + wid * chunk;
        int c1 = min(c0 + chunk, lo + cnt);
        if (c0 < c1) {
            // sliding 5-wide state window: 1 new LDS per cell
            float w0 = sin_[(c0 + 12) * 32 + lane];
            float w1 = sin_[(c0 + 13) * 32 + lane];
            float w2 = sin_[(c0 + 14) * 32 + lane];
            float w3 = sin_[(c0 + 15) * 32 + lane];
            #pragma unroll 2
            for (int cell = c0; cell < c1; cell++) {
                float w4 = sin_[(cell + 16) * 32 + lane];
                // table: 32 floats = 16 packed pairs via 8x 16B shared loads (warp-uniform)
                const ulonglong2* tp = (const ulonglong2*)(twb + (cell + 14) * 36);
                unsigned long long t[16];
                #pragma unroll
                for (int k = 0; k < 8; k++) {
                    ulonglong2 q = tp[k];
                    t[2 * k] = q.x; t[2 * k + 1] = q.y;
                }
                unsigned long long s0p = pk2(w0), o0p = pk2(1.0f - w0);
                unsigned long long s1p = pk2(w1), o1p = pk2(1.0f - w1);
                unsigned long long s2p = pk2(w2), o2p = pk2(1.0f - w2);
                unsigned long long s3p = pk2(w3), o3p = pk2(1.0f - w3);
                // fold MSB->LSB: neighbor -2 (bit16), -1 (bit8), 0 (bit4), +1 (bit2); +2 (bit1) scalar
                #pragma unroll
                for (int k = 0; k < 8; k++) t[k] = pklerp(t[k], t[k + 8], o0p, s0p);
                #pragma unroll
                for (int k = 0; k < 4; k++) t[k] = pklerp(t[k], t[k + 4], o1p, s1p);
                t[0] = pklerp(t[0], t[2], o2p, s2p);
                t[1] = pklerp(t[1], t[3], o2p, s2p);
                t[0] = pklerp(t[0], t[1], o3p, s3p);
                float z0, z1;
                asm("mov.b64 {%0, %1}, %2;" : "=f"(z0), "=f"(z1) : "l"(t[0]));
                float res = __saturatef(lerpf(z0, z1, w4));
                sout[(cell + 14) * 32 + lane] = res;
                w0 = w1; w1 = w2; w2 = w3; w3 = w4;
            }
        }
        cur ^= 1;
    }
    __syncthreads();

    // ---- output: out[b][m] = state[4m] for 4m in [start, start+T) ----
    const float* sf = s_state + cur * srows * 32;
    const int m0  = (start + 3) >> 2;
    const int nmo = ((start + T + 3) >> 2) - m0;
    for (int mi0 = 0; mi0 < nmo; mi0 += 16) {
        for (int i = tid; i < 32 * 16; i += NTHREADS) {
            int mi = mi0 + (i & 15), bb = i >> 4;
            if (mi < nmo) {
                int m = m0 + mi;
                out[bb * MX + m] = sf[(4 * m - start + 14) * 32 + bb];
            }
        }
    }
}

extern "C" void kernel_launch(void* const* d_in, const int* in_sizes, int n_in,
                              void* d_out, int out_size)
{
    const float* x  = (const float*)d_in[0];
    const float* tg = (const float*)d_in[1];
    float* out = (float*)d_out;

    const int nblk  = NBLK;
    const int base  = GRIDN / nblk;          // 55
    const int extra = GRIDN - base * nblk;   // 104
    const int tmax  = base + 1;              // 56
    const int srows = tmax + 28;             // 84
    const int nx    = tmax / 4 + 11;         // 25
    size_t smem = (size_t)(2 * srows * 32 + 2 * srows * 36 + nx * 33) * sizeof(float); // ~49 KB

    static int smem_set = 0;
    if (!smem_set) {
        cudaFuncSetAttribute(ASIC_44186623541335_kernel,
                             cudaFuncAttributeMaxDynamicSharedMemorySize, (int)smem);
        smem_set = 1;
    }
    ASIC_44186623541335_kernel<<<nblk, NTHREADS, smem>>>(x, tg, out, base, extra, srows);
}

// round 11
// speedup vs baseline: 1.9004x; 1.0089x over previous
#include <cuda_runtime.h>

#define GRIDN 16384
#define GMASK 16383
#define MX    4096
#define NLAYER 8
#define NTHREADS 512
#define NWARP 16
#define NBLK 296   // 2 * 148; single wave on both 148- and 152-SM sm_103a parts

__device__ __forceinline__ float sigf(float v) {
    return __fdividef(1.0f, 1.0f + __expf(-v));
}

__device__ __forceinline__ float lerpf(float a, float b, float w) {
    return fmaf(w, b - a, a);   // a + w*(b-a)
}

__device__ __forceinline__ unsigned long long pk2(float a) {
    unsigned long long r;
    asm("mov.b64 %0, {%1, %2};" : "=l"(r) : "f"(a), "f"(a));
    return r;
}

// packed lerp, fma-only: r = lo + s*(hi-lo); neg1 = packed -1.0f (loop-invariant)
__device__ __forceinline__ unsigned long long plerp(unsigned long long lo, unsigned long long hi,
                                                    unsigned long long sp, unsigned long long neg1) {
    unsigned long long d, r;
    asm("fma.rn.f32x2 %0, %1, %2, %3;" : "=l"(d) : "l"(lo), "l"(neg1), "l"(hi));  // hi - lo
    asm("fma.rn.f32x2 %0, %1, %2, %3;" : "=l"(r) : "l"(d),  "l"(sp),   "l"(lo));  // lo + s*d
    return r;
}

__global__ __launch_bounds__(NTHREADS, 2)
void ASIC_44186623541335_kernel(const float* __restrict__ x, const float* __restrict__ tg,
                                float* __restrict__ out, int base, int extra, int srows)
{
    extern __shared__ float sm[];
    float* s_state = sm;                      // 2 * srows * 32 (ping-pong, [cell][batch])
    float* s_tw    = sm + 2 * srows * 32;     // 2 * srows * 36 (double-buffered, [cell][c])
    float* s_x     = s_tw + 2 * srows * 36;   // [m][batch] pitch 33

    const int blk  = blockIdx.x;
    const int T    = base + (blk < extra ? 1 : 0);
    const int start = blk * base + (blk < extra ? blk : extra);
    const int tid  = threadIdx.x;
    const int lane = tid & 31;   // lane == batch index
    const int wid  = tid >> 5;

    // prefetch mapping for tw staging: c = tid>>4 (0..31), r = (tid&15) + 16k, k<5 (covers cnt<=80)
    const int pc  = tid >> 4;
    const int pr0 = tid & 15;
    const float* tg_pc = tg + pc * GRIDN;
    float v[5];

    // ---- prologue: issue LDGs for layer 1's tables (latency hidden by x-stage + layer0) ----
    {
        const int h = 12, cnt = T + 24;               // layer 1 halo
        const float* tgl = tg_pc + 1 * (32 * GRIDN);
        #pragma unroll
        for (int k = 0; k < 5; k++) {
            int r = pr0 + 16 * k;
            if (r < cnt) v[k] = tgl[(start - h + r) & GMASK];
        }
    }

    // ---- stage x tile (m window with ring wrap), [m][batch] pitch 33 ----
    const int m_lo = (start - 16) >> 2;                   // arithmetic floor
    const int nmv  = ((start + T + 15) >> 2) - m_lo + 1;
    for (int mi0 = 0; mi0 < nmv; mi0 += 32) {
        for (int i = tid; i < 32 * 32; i += NTHREADS) {
            int mi = mi0 + (i & 31), bb = i >> 5;
            if (mi < nmv) {
                int m = (m_lo + mi) & (MX - 1);
                s_x[mi * 33 + bb] = x[bb * MX + m];
            }
        }
    }
    __syncthreads();

    // ---- layer 0: initial state is x at every 4th cell, zeros elsewhere.
    // Zero fold-weights select table entries -> 1..3 lerps, 2..4 table loads.
    {
        const int lo = -14;
        const int cnt = T + 28;
        const int chunk = (cnt + NWARP - 1) / NWARP;
        int c0 = lo + wid * chunk;
        int c1 = min(c0 + chunk, lo + cnt);
        for (int rel = c0; rel < c1; rel++) {
            int graw = start + rel;
            int g = graw & GMASK;
            int r4 = graw & 3;
            float t0 = sigf(tg[g]);
            float res;
            if (r4 == 2) {  // two nonzero neighbors: i=0 (bit 16) and i=4 (bit 1)
                float t16 = sigf(tg[16 * GRIDN + g]);
                float t1  = sigf(tg[1  * GRIDN + g]);
                float t17 = sigf(tg[17 * GRIDN + g]);
                float sa = s_x[(((graw - 2) >> 2) - m_lo) * 33 + lane];
                float sb = s_x[(((graw + 2) >> 2) - m_lo) * 33 + lane];
                float a = lerpf(t0, t16, sa);
                float b = lerpf(t1, t17, sa);
                res = lerpf(a, b, sb);
            } else {
                int cidx, doff;
                if (r4 == 0)      { cidx = 4; doff =  0; }  // i=2 -> bit 4
                else if (r4 == 1) { cidx = 8; doff = -1; }  // i=1 -> bit 8
                else              { cidx = 2; doff =  1; }  // i=3 -> bit 2
                float t1 = sigf(tg[cidx * GRIDN + g]);
                float s = s_x[(((graw + doff) >> 2) - m_lo) * 33 + lane];
                res = lerpf(t0, t1, s);
            }
            s_state[(rel + 14) * 32 + lane] = __saturatef(res);
        }
    }

    // ---- layers 1..7: pipelined staging (1 barrier/layer), packed fma-only fold ----
    const unsigned long long neg1 = pk2(-1.0f);
    int cur = 0;
    for (int l = 1; l < NLAYER; l++) {
        const int h = 2 * (NLAYER - 1 - l);
        const int lo = -h;
        const int cnt = T + 2 * h;
        float* twb = s_tw + (l & 1) * srows * 36;

        // store prefetched tables (sigmoid applied) into this layer's buffer
        #pragma unroll
        for (int k = 0; k < 5; k++) {
            int r = pr0 + 16 * k;
            if (r < cnt) twb[(lo + r + 14) * 36 + pc] = sigf(v[k]);
        }
        // issue LDGs for next layer's tables; latency drains under the fold below
        if (l < NLAYER - 1) {
            const int hn = h - 2, cntn = cnt - 4;
            const float* tgln = tg_pc + (l + 1) * (32 * GRIDN);
            #pragma unroll
            for (int k = 0; k < 5; k++) {
                int r = pr0 + 16 * k;
                if (r < cntn) v[k] = tgln[(start - hn + r) & GMASK];
            }
        }
        __syncthreads();   // tw[l] visible + state[l-1] complete

        const float* sin_ = s_state + cur * srows * 32;
        float*       sout = s_state + (cur ^ 1) * srows * 32;
        const int chunk = (cnt + NWARP - 1) / NWARP;
        int c0 = lo + wid * chunk;
        int c1 = min(c0 + chunk, lo + cnt);
        if (c0 < c1) {
            // sliding 5-wide state window: 1 new LDS per cell
            float w0 = sin_[(c0 + 12) * 32 + lane];
            float w1 = sin_[(c0 + 13) * 32 + lane];
            float w2 = sin_[(c0 + 14) * 32 + lane];
            float w3 = sin_[(c0 + 15) * 32 + lane];
            #pragma unroll 2
            for (int cell = c0; cell < c1; cell++) {
                float w4 = sin_[(cell + 16) * 32 + lane];
                // table: 16 packed pairs; fold level 1 fused with loads (max 16 live table regs)
                const ulonglong2* tp = (const ulonglong2*)(twb + (cell + 14) * 36);
                unsigned long long s0p = pk2(w0), s1p = pk2(w1);
                unsigned long long s2p = pk2(w2), s3p = pk2(w3);
                unsigned long long u[8];
                // level 1 (neighbor -2): t[k] vs t[k+8]; tp[j]=(t[2j],t[2j+1]), tp[j+4]=(t[2j+8],t[2j+9])
                #pragma unroll
                for (int j = 0; j < 4; j++) {
                    ulonglong2 qa = tp[j];
                    ulonglong2 qb = tp[j + 4];
                    u[2 * j]     = plerp(qa.x, qb.x, s0p, neg1);
                    u[2 * j + 1] = plerp(qa.y, qb.y, s0p, neg1);
                }
                // level 2 (neighbor -1): u[k] vs u[k+4]
                #pragma unroll
                for (int k = 0; k < 4; k++) u[k] = plerp(u[k], u[k + 4], s1p, neg1);
                // level 3 (center): u[k] vs u[k+2]
                u[0] = plerp(u[0], u[2], s2p, neg1);
                u[1] = plerp(u[1], u[3], s2p, neg1);
                // level 4 (neighbor +1)
                u[0] = plerp(u[0], u[1], s3p, neg1);
                float z0, z1;
                asm("mov.b64 {%0, %1}, %2;" : "=f"(z0), "=f"(z1) : "l"(u[0]));
                // level 5 (neighbor +2), scalar
                float res = __saturatef(lerpf(z0, z1, w4));
                sout[(cell + 14) * 32 + lane] = res;
                w0 = w1; w1 = w2; w2 = w3; w3 = w4;
            }
        }
        cur ^= 1;
    }
    __syncthreads();

    // ---- output: out[b][m] = state[4m] for 4m in [start, start+T) ----
    const float* sf = s_state + cur * srows * 32;
    const int m0  = (start + 3) >> 2;
    const int nmo = ((start + T + 3) >> 2) - m0;
    for (int mi0 = 0; mi0 < nmo; mi0 += 16) {
        for (int i = tid; i < 32 * 16; i += NTHREADS) {
            int mi = mi0 + (i & 15), bb = i >> 4;
            if (mi < nmo) {
                int m = m0 + mi;
                out[bb * MX + m] = sf[(4 * m - start + 14) * 32 + bb];
            }
        }
    }
}

extern "C" void kernel_launch(void* const* d_in, const int* in_sizes, int n_in,
                              void* d_out, int out_size)
{
    const float* x  = (const float*)d_in[0];
    const float* tg = (const float*)d_in[1];
    float* out = (float*)d_out;

    const int nblk  = NBLK;
    const int base  = GRIDN / nblk;          // 55
    const int extra = GRIDN - base * nblk;   // 104
    const int tmax  = base + 1;              // 56
    const int srows = tmax + 28;             // 84
    const int nx    = tmax / 4 + 11;         // 25
    size_t smem = (size_t)(2 * srows * 32 + 2 * srows * 36 + nx * 33) * sizeof(float); // ~49 KB

    static int smem_set = 0;
    if (!smem_set) {
        cudaFuncSetAttribute(ASIC_44186623541335_kernel,
                             cudaFuncAttributeMaxDynamicSharedMemorySize, (int)smem);
        smem_set = 1;
    }
    ASIC_44186623541335_kernel<<<nblk, NTHREADS, smem>>>(x, tg, out, base, extra, srows);
}